// round 4
// baseline (speedup 1.0000x reference)
#include <cuda_runtime.h>
#include <cuda_bf16.h>
#include <math.h>

// Problem dims (fixed by the dataset)
#define HH 768
#define G3 2304          // 3*H
#define BB 64            // batch
#define LL 512           // seq len
#define NSTEP 513        // 512 sequence steps + 1 final (end-token) step
#define NROWS (NSTEP*BB) // 32832

#define NBLK 144         // persistent blocks (<=148 SMs -> co-resident)
#define TPB  128
#define NCOL 16          // gh cols per block: G3 / NBLK
#define CHK  128         // k-chunk rows staged per buffer

// Scratch (device globals — allocation-free rule)
static __device__ __align__(256) float g_gi[(size_t)NROWS * G3];   // precomputed input gates
static __device__ __align__(256) float g_gh[BB * G3];              // recurrent gate pre-activations
static __device__ __align__(256) float g_hT[HH * BB];              // h transposed [k][b]
static __device__ __align__(256) float g_hbm[BB * HH];             // h [b][k]
static __device__ __align__(256) float g_s1[BB * HH];              // scorer layer1 out
static __device__ __align__(256) float g_s2[BB * HH];              // scorer layer2 out
static __device__ unsigned g_count = 0;                            // monotonic barrier counter
static __device__ unsigned g_gen   = 0;                            // monotonic generation

// ---------------------------------------------------------------------------
// packed fp32 helpers (sm_103a f32x2)
__device__ __forceinline__ void ffma2(unsigned long long& d,
                                      unsigned long long a, unsigned long long b)
{
    asm("fma.rn.f32x2 %0, %1, %2, %0;" : "+l"(d) : "l"(a), "l"(b));
}
__device__ __forceinline__ unsigned long long pack2(float x)
{
    unsigned long long r;
    asm("mov.b64 %0, {%1, %1};" : "=l"(r) : "f"(x));
    return r;
}
__device__ __forceinline__ float2 unpk2(unsigned long long v)
{
    float2 f;
    asm("mov.b64 {%0, %1}, %2;" : "=f"(f.x), "=f"(f.y) : "l"(v));
    return f;
}
__device__ __forceinline__ void cpa16(unsigned dst, const void* src)
{
    asm volatile("cp.async.cg.shared.global [%0], [%1], 16;" :: "r"(dst), "l"(src));
}
__device__ __forceinline__ void cpa_commit() { asm volatile("cp.async.commit_group;" ::: "memory"); }
__device__ __forceinline__ void cpa_wait0()  { asm volatile("cp.async.wait_group 0;" ::: "memory"); }

// ---------------------------------------------------------------------------
__global__ void k_init()
{
    int t = blockIdx.x * blockDim.x + threadIdx.x;
    if (t < BB * HH) { g_hT[t] = 0.f; g_hbm[t] = 0.f; }
}

// ---------------------------------------------------------------------------
// gi = relu_if_seq(emb[token]) @ w_ih.T + b_ih
// Block tile 64 rows x 128 cols, 64 threads, thread tile 16x8 (f32x2 pairs along M).
__global__ void __launch_bounds__(64) k_gi(const int* __restrict__ goal,
                                           const float* __restrict__ emb,
                                           const float* __restrict__ w_ih,
                                           const float* __restrict__ b_ih)
{
    __shared__ __align__(16) float As[16][64];
    __shared__ __align__(16) float Bs[16][128];
    __shared__ int tok[64];

    const int by  = blockIdx.y;        // step index
    const int n0  = blockIdx.x * 128;  // output-col base
    const int tid = threadIdx.x;       // 64 threads
    const bool seq = (by < LL);

    tok[tid] = seq ? goal[tid * LL + by] : 1;
    __syncthreads();

    const int mg = tid >> 4;           // 0..3  -> rows mg*16..+15
    const int ng = tid & 15;           // 0..15 -> cols ng*8..+7

    unsigned long long acc[8][8];
#pragma unroll
    for (int p = 0; p < 8; p++)
#pragma unroll
        for (int c = 0; c < 8; c++) acc[p][c] = 0ull;

    for (int k0 = 0; k0 < HH; k0 += 16) {
#pragma unroll
        for (int j = 0; j < 4; j++) {          // As: 64 rows x 16 k
            int f  = tid + 64 * j;
            int r  = f >> 2;
            int kk = (f & 3) * 4;
            float4 v = *(const float4*)(emb + (size_t)tok[r] * HH + k0 + kk);
            if (seq) { v.x = fmaxf(v.x, 0.f); v.y = fmaxf(v.y, 0.f);
                       v.z = fmaxf(v.z, 0.f); v.w = fmaxf(v.w, 0.f); }
            As[kk][r] = v.x; As[kk+1][r] = v.y; As[kk+2][r] = v.z; As[kk+3][r] = v.w;
        }
#pragma unroll
        for (int j = 0; j < 8; j++) {          // Bs: 128 cols x 16 k
            int f  = tid + 64 * j;
            int r  = f >> 2;
            int kk = (f & 3) * 4;
            float4 w = *(const float4*)(w_ih + (size_t)(n0 + r) * HH + k0 + kk);
            Bs[kk][r] = w.x; Bs[kk+1][r] = w.y; Bs[kk+2][r] = w.z; Bs[kk+3][r] = w.w;
        }
        __syncthreads();
#pragma unroll 4
        for (int k = 0; k < 16; k++) {
            ulonglong2 a0 = *(const ulonglong2*)&As[k][mg * 16];
            ulonglong2 a1 = *(const ulonglong2*)&As[k][mg * 16 + 4];
            ulonglong2 a2 = *(const ulonglong2*)&As[k][mg * 16 + 8];
            ulonglong2 a3 = *(const ulonglong2*)&As[k][mg * 16 + 12];
            float4 w0 = *(const float4*)&Bs[k][ng * 8];
            float4 w1 = *(const float4*)&Bs[k][ng * 8 + 4];
            unsigned long long ap[8] = {a0.x, a0.y, a1.x, a1.y, a2.x, a2.y, a3.x, a3.y};
            unsigned long long bp[8] = {pack2(w0.x), pack2(w0.y), pack2(w0.z), pack2(w0.w),
                                        pack2(w1.x), pack2(w1.y), pack2(w1.z), pack2(w1.w)};
#pragma unroll
            for (int p = 0; p < 8; p++)
#pragma unroll
                for (int c = 0; c < 8; c++) ffma2(acc[p][c], ap[p], bp[c]);
        }
        __syncthreads();
    }

    const int rowBase = by * BB;
#pragma unroll
    for (int p = 0; p < 8; p++) {
        const int r0 = rowBase + mg * 16 + 2 * p;
        float* d0 = g_gi + (size_t)r0 * G3 + n0 + ng * 8;
        float* d1 = d0 + G3;
#pragma unroll
        for (int c = 0; c < 8; c++) {
            float2 v = unpk2(acc[p][c]);
            float bias = b_ih[n0 + ng * 8 + c];
            d0[c] = v.x + bias;
            d1[c] = v.y + bias;
        }
    }
}

// ---------------------------------------------------------------------------
// software grid barrier (monotonic, replay-safe)
__device__ __forceinline__ void gsync()
{
    __threadfence();
    __syncthreads();
    if (threadIdx.x == 0) {
        unsigned old = atomicAdd(&g_count, 1u) + 1u;
        if (old % NBLK == 0u) {
            atomicAdd(&g_gen, 1u);
        } else {
            unsigned target = (old + NBLK - 1u) / NBLK;
            volatile unsigned* vg = &g_gen;
            while (*vg < target) __nanosleep(20);
        }
    }
    __syncthreads();
}

__device__ __forceinline__ float sigmoidf_(float x)
{
    return 1.f / (1.f + __expf(-x));
}

// ---------------------------------------------------------------------------
// Persistent recurrence. 144 blocks x 128 threads, 16 gh-cols each.
// ws (w_hh slice, [768][16]) resident in smem for all steps.
// h staged via double-buffered cp.async chunks of 128 k.
// Thread tile 16 rows x 8 cols (f32x2), k-split 16 within chunk.
// dyn smem: ws 48KB + hs 2x32KB = 112KB.
__global__ void __launch_bounds__(TPB, 1) k_rec(const float* __restrict__ w_hh,
                                                const float* __restrict__ b_hh)
{
    extern __shared__ __align__(16) float smem[];
    float* ws = smem;                    // [768][16]
    float* hs = smem + HH * NCOL;        // [2][128][64]

    const int tid = threadIdx.x;
    const int n0  = blockIdx.x * NCOL;
    const int ks  = tid >> 3;            // 0..15 k-split
    const int sub = tid & 7;
    const int mg  = sub >> 1;            // rows mg*16..+15
    const int ng  = sub & 1;             // cols ng*8..+7

    // preload w slice: ws[k][c] = w_hh[n0+c][k]
    for (int idx = tid; idx < NCOL * HH; idx += TPB) {
        int k = idx >> 4, c = idx & 15;
        ws[k * NCOL + c] = w_hh[(size_t)(n0 + c) * HH + k];
    }
    __syncthreads();

    const unsigned hs_base = (unsigned)__cvta_generic_to_shared(hs);
    const int gtid = blockIdx.x * TPB + tid;

    for (int l = 0; l < NSTEP; l++) {
        // prologue: stage chunk 0
        {
            const float* src = g_hT + tid * 4;
            unsigned dst = hs_base + tid * 16;
#pragma unroll
            for (int j = 0; j < 16; j++)
                cpa16(dst + j * TPB * 16, src + (size_t)j * TPB * 4);
            cpa_commit();
            cpa_wait0();
            __syncthreads();
        }

        unsigned long long acc[8][8];
#pragma unroll
        for (int p = 0; p < 8; p++)
#pragma unroll
            for (int c = 0; c < 8; c++) acc[p][c] = 0ull;

        for (int ch = 0; ch < HH / CHK; ch++) {
            if (ch < HH / CHK - 1) {   // prefetch next chunk into other buffer
                const float* src = g_hT + (size_t)(ch + 1) * CHK * BB + tid * 4;
                unsigned dst = hs_base + ((ch + 1) & 1) * (CHK * BB * 4) + tid * 16;
#pragma unroll
                for (int j = 0; j < 16; j++)
                    cpa16(dst + j * TPB * 16, src + (size_t)j * TPB * 4);
                cpa_commit();
            }
            const float* hb = hs + (ch & 1) * (CHK * BB);
#pragma unroll
            for (int i = 0; i < 8; i++) {
                const int kl = ks * 8 + i;          // local k within chunk
                const int kg = ch * CHK + kl;       // global k
                ulonglong2 a0 = *(const ulonglong2*)&hb[kl * BB + mg * 16];
                ulonglong2 a1 = *(const ulonglong2*)&hb[kl * BB + mg * 16 + 4];
                ulonglong2 a2 = *(const ulonglong2*)&hb[kl * BB + mg * 16 + 8];
                ulonglong2 a3 = *(const ulonglong2*)&hb[kl * BB + mg * 16 + 12];
                float4 w0 = *(const float4*)&ws[kg * NCOL + ng * 8];
                float4 w1 = *(const float4*)&ws[kg * NCOL + ng * 8 + 4];
                unsigned long long ap[8] = {a0.x, a0.y, a1.x, a1.y, a2.x, a2.y, a3.x, a3.y};
                unsigned long long bp[8] = {pack2(w0.x), pack2(w0.y), pack2(w0.z), pack2(w0.w),
                                            pack2(w1.x), pack2(w1.y), pack2(w1.z), pack2(w1.w)};
#pragma unroll
                for (int p = 0; p < 8; p++)
#pragma unroll
                    for (int c = 0; c < 8; c++) ffma2(acc[p][c], ap[p], bp[c]);
            }
            cpa_wait0();
            __syncthreads();
        }

        // ---- k-split reduction in smem (reuse hs: red[16][64][16]) ----
        float* red = hs;
#pragma unroll
        for (int p = 0; p < 8; p++) {
            const int r0 = mg * 16 + 2 * p;
#pragma unroll
            for (int c = 0; c < 8; c++) {
                float2 v = unpk2(acc[p][c]);
                red[ks * 1024 + r0 * 16 + ng * 8 + c]       = v.x;
                red[ks * 1024 + (r0 + 1) * 16 + ng * 8 + c] = v.y;
            }
        }
        __syncthreads();
        {
            float4 s0 = make_float4(0, 0, 0, 0), s1 = s0;
#pragma unroll
            for (int s = 0; s < 16; s++) {
                float4 v0 = *(const float4*)&red[s * 1024 + tid * 8];
                float4 v1 = *(const float4*)&red[s * 1024 + tid * 8 + 4];
                s0.x += v0.x; s0.y += v0.y; s0.z += v0.z; s0.w += v0.w;
                s1.x += v1.x; s1.y += v1.y; s1.z += v1.z; s1.w += v1.w;
            }
            const int m    = tid >> 1;              // batch row
            const int col0 = n0 + (tid & 1) * 8;    // global gh col
            __stcg((float4*)(g_gh + (size_t)m * G3 + col0), s0);
            __stcg((float4*)(g_gh + (size_t)m * G3 + col0 + 4), s1);
        }

        gsync();

        // ---- gate phase ----
        for (int t = gtid; t < BB * HH; t += NBLK * TPB) {
            const int b = t / HH;
            const int j = t - b * HH;
            const float* ghp = g_gh + (size_t)b * G3;
            float ghr = __ldcg(ghp + j);
            float ghz = __ldcg(ghp + j + HH);
            float ghn = __ldcg(ghp + j + 2 * HH);
            const float* gi = g_gi + ((size_t)l * BB + b) * G3;
            float r = sigmoidf_(gi[j]      + ghr + b_hh[j]);
            float z = sigmoidf_(gi[j + HH] + ghz + b_hh[j + HH]);
            float n = tanhf(gi[j + 2 * HH] + r * (ghn + b_hh[j + 2 * HH]));
            float hold = __ldcg(&g_hbm[t]);
            float h = (1.f - z) * n + z * hold;
            if (l < LL) h = fmaxf(h, 0.f);
            __stcg(&g_hbm[t], h);
            __stcg(&g_hT[j * BB + b], h);
        }

        gsync();
    }
}

// ---------------------------------------------------------------------------
// Scorer layers — kernels reference device globals DIRECTLY (device-side
// symbol access; passing __device__ globals from host code is invalid and
// was the R3 bug).
__global__ void __launch_bounds__(256) k_mlp0(const float* __restrict__ w,
                                              const float* __restrict__ bias)
{
    const int warp = threadIdx.x >> 5;
    const int lane = threadIdx.x & 31;
    const int n = blockIdx.x * 8 + warp;           // neuron

    float4 wr[6];
    const float* wrow = w + (size_t)n * HH + lane * 24;
#pragma unroll
    for (int i = 0; i < 6; i++) wr[i] = *(const float4*)(wrow + i * 4);
    const float bn = bias[n];

    for (int b = 0; b < BB; b++) {
        const float* xr = g_hbm + (size_t)b * HH + lane * 24;
        float s = 0.f;
#pragma unroll
        for (int i = 0; i < 6; i++) {
            float4 xv = *(const float4*)(xr + i * 4);
            s += xv.x * wr[i].x + xv.y * wr[i].y + xv.z * wr[i].z + xv.w * wr[i].w;
        }
#pragma unroll
        for (int off = 16; off; off >>= 1) s += __shfl_xor_sync(0xffffffffu, s, off);
        if (lane == 0) g_s1[(size_t)b * HH + n] = fmaxf(s + bn, 0.f);
    }
}

__global__ void __launch_bounds__(256) k_mlp1(const float* __restrict__ w,
                                              const float* __restrict__ bias)
{
    const int warp = threadIdx.x >> 5;
    const int lane = threadIdx.x & 31;
    const int n = blockIdx.x * 8 + warp;

    float4 wr[6];
    const float* wrow = w + (size_t)n * HH + lane * 24;
#pragma unroll
    for (int i = 0; i < 6; i++) wr[i] = *(const float4*)(wrow + i * 4);
    const float bn = bias[n];

    for (int b = 0; b < BB; b++) {
        const float* xr = g_s1 + (size_t)b * HH + lane * 24;
        float s = 0.f;
#pragma unroll
        for (int i = 0; i < 6; i++) {
            float4 xv = *(const float4*)(xr + i * 4);
            s += xv.x * wr[i].x + xv.y * wr[i].y + xv.z * wr[i].z + xv.w * wr[i].w;
        }
#pragma unroll
        for (int off = 16; off; off >>= 1) s += __shfl_xor_sync(0xffffffffu, s, off);
        if (lane == 0) g_s2[(size_t)b * HH + n] = fmaxf(s + bn, 0.f);
    }
}

// final: out[b] = y2[b] . swo + sbo
__global__ void __launch_bounds__(256) k_final(const float* __restrict__ swo,
                                               const float* __restrict__ sbo,
                                               float* __restrict__ out)
{
    const int warp = threadIdx.x >> 5;
    const int lane = threadIdx.x & 31;
    const int b = blockIdx.x * 8 + warp;
    const float* xr = g_s2 + (size_t)b * HH + lane * 24;
    const float* wr = swo + lane * 24;
    float s = 0.f;
#pragma unroll
    for (int i = 0; i < 6; i++) {
        float4 xv = *(const float4*)(xr + i * 4);
        float4 wv = *(const float4*)(wr + i * 4);
        s += xv.x * wv.x + xv.y * wv.y + xv.z * wv.z + xv.w * wv.w;
    }
#pragma unroll
    for (int off = 16; off; off >>= 1) s += __shfl_xor_sync(0xffffffffu, s, off);
    if (lane == 0) out[b] = s + sbo[0];
}

// ---------------------------------------------------------------------------
extern "C" void kernel_launch(void* const* d_in, const int* in_sizes, int n_in,
                              void* d_out, int out_size)
{
    const int*   goal = (const int*)  d_in[0];
    const float* emb  = (const float*)d_in[1];
    const float* w_ih = (const float*)d_in[2];
    const float* w_hh = (const float*)d_in[3];
    const float* b_ih = (const float*)d_in[4];
    const float* b_hh = (const float*)d_in[5];
    const float* sw0  = (const float*)d_in[6];
    const float* sb0  = (const float*)d_in[7];
    const float* sw1  = (const float*)d_in[8];
    const float* sb1  = (const float*)d_in[9];
    const float* swo  = (const float*)d_in[10];
    const float* sbo  = (const float*)d_in[11];
    float* out = (float*)d_out;

    const int smem_rec = (HH * NCOL + 2 * CHK * BB) * (int)sizeof(float); // 112KB
    cudaFuncSetAttribute(k_rec, cudaFuncAttributeMaxDynamicSharedMemorySize, smem_rec);

    k_init<<<(BB * HH + 255) / 256, 256>>>();
    k_gi<<<dim3(G3 / 128, NSTEP), 64>>>(goal, emb, w_ih, b_ih);
    k_rec<<<NBLK, TPB, smem_rec>>>(w_hh, b_hh);
    k_mlp0<<<HH / 8, 256>>>(sw0, sb0);
    k_mlp1<<<HH / 8, 256>>>(sw1, sb1);
    k_final<<<BB / 8, 256>>>(swo, sbo, out);
}

// round 6
// speedup vs baseline: 1.5335x; 1.5335x over previous
#include <cuda_runtime.h>
#include <cuda_bf16.h>
#include <math.h>

// Problem dims (fixed)
#define HH 768
#define G3 2304          // 3*H
#define BB 64            // batch
#define LL 512           // seq len
#define NSTEP 513        // 512 steps + final end-token step
#define NROWS (NSTEP*BB)

// recurrence kernel config
#define RBLK 96          // blocks; each owns UPB hidden units
#define RTPB 256
#define UPB  8           // hidden units per block
#define RC   24          // gh cols per block = 3*UPB
#define CHK  256         // staged k rows per buffer (768 = 3*256)

// Scratch (device globals — allocation-free rule)
static __device__ __align__(256) float g_gi[(size_t)NROWS * G3];   // precomputed input gates
static __device__ __align__(256) float g_hT[HH * BB];              // h transposed [k][b]
static __device__ __align__(256) float g_hbm[BB * HH];             // final h [b][k] for scorer
static __device__ __align__(256) float g_s1[BB * HH];
static __device__ __align__(256) float g_s2[BB * HH];
static __device__ unsigned g_count = 0;
static __device__ unsigned g_gen   = 0;

// ---------------------------------------------------------------------------
// packed fp32 helpers (sm_103a f32x2)
__device__ __forceinline__ void ffma2(unsigned long long& d,
                                      unsigned long long a, unsigned long long b)
{
    asm("fma.rn.f32x2 %0, %1, %2, %0;" : "+l"(d) : "l"(a), "l"(b));
}
__device__ __forceinline__ unsigned long long pack2(float x)
{
    unsigned long long r;
    asm("mov.b64 %0, {%1, %1};" : "=l"(r) : "f"(x));
    return r;
}
__device__ __forceinline__ float2 unpk2(unsigned long long v)
{
    float2 f;
    asm("mov.b64 {%0, %1}, %2;" : "=f"(f.x), "=f"(f.y) : "l"(v));
    return f;
}
__device__ __forceinline__ void cpa16(unsigned dst, const void* src)
{
    asm volatile("cp.async.cg.shared.global [%0], [%1], 16;" :: "r"(dst), "l"(src));
}
__device__ __forceinline__ void cpa_commit() { asm volatile("cp.async.commit_group;" ::: "memory"); }
__device__ __forceinline__ void cpa_wait0()  { asm volatile("cp.async.wait_group 0;" ::: "memory"); }
__device__ __forceinline__ void cpa_wait1()  { asm volatile("cp.async.wait_group 1;" ::: "memory"); }

__device__ __forceinline__ float sigmoidf_(float x)
{
    return 1.f / (1.f + __expf(-x));
}

// ---------------------------------------------------------------------------
__global__ void k_init()
{
    int t = blockIdx.x * blockDim.x + threadIdx.x;
    if (t < BB * HH) g_hT[t] = 0.f;
}

// ---------------------------------------------------------------------------
// gi = relu_if_seq(emb[token]) @ w_ih.T + b_ih
// Block tile 64 rows x 128 cols, 128 threads, thread tile 8r(4 f32x2 pairs) x 8c.
// Register double-buffered global loads (hide DRAM latency of emb gathers).
__global__ void __launch_bounds__(128) k_gi(const int* __restrict__ goal,
                                            const float* __restrict__ emb,
                                            const float* __restrict__ w_ih,
                                            const float* __restrict__ b_ih)
{
    __shared__ __align__(16) float As[16][64];
    __shared__ __align__(16) float Bs[16][128];
    __shared__ int tok[64];

    const int by  = blockIdx.y;
    const int n0  = blockIdx.x * 128;
    const int tid = threadIdx.x;
    const bool seq = (by < LL);

    if (tid < 64) tok[tid] = seq ? goal[tid * LL + by] : 1;
    __syncthreads();

    const int mg = tid >> 4;      // 0..7 -> rows mg*8..+7
    const int ng = tid & 15;      // 0..15 -> cols ng*8..+7

    // load helpers: A 2 float4/thread, B 4 float4/thread per 16-k tile
    const int fa0 = tid,          fa1 = tid + 128;
    const int ra0 = fa0 >> 2,     ra1 = fa1 >> 2;
    const int ka0 = (fa0 & 3)*4,  ka1 = (fa1 & 3)*4;

    float4 va[2], vb[4];
    auto loadA = [&](float4 v[2], int k0) {
        v[0] = *(const float4*)(emb + (size_t)tok[ra0] * HH + k0 + ka0);
        v[1] = *(const float4*)(emb + (size_t)tok[ra1] * HH + k0 + ka1);
        if (seq) {
#pragma unroll
            for (int q = 0; q < 2; q++) {
                v[q].x = fmaxf(v[q].x, 0.f); v[q].y = fmaxf(v[q].y, 0.f);
                v[q].z = fmaxf(v[q].z, 0.f); v[q].w = fmaxf(v[q].w, 0.f);
            }
        }
    };
    auto loadB = [&](float4 v[4], int k0) {
#pragma unroll
        for (int q = 0; q < 4; q++) {
            int f = tid + 128 * q;
            int r = f >> 2, kk = (f & 3) * 4;
            v[q] = *(const float4*)(w_ih + (size_t)(n0 + r) * HH + k0 + kk);
        }
    };
    auto storeA = [&](const float4 v[2]) {
        As[ka0][ra0] = v[0].x; As[ka0+1][ra0] = v[0].y; As[ka0+2][ra0] = v[0].z; As[ka0+3][ra0] = v[0].w;
        As[ka1][ra1] = v[1].x; As[ka1+1][ra1] = v[1].y; As[ka1+2][ra1] = v[1].z; As[ka1+3][ra1] = v[1].w;
    };
    auto storeB = [&](const float4 v[4]) {
#pragma unroll
        for (int q = 0; q < 4; q++) {
            int f = tid + 128 * q;
            int r = f >> 2, kk = (f & 3) * 4;
            Bs[kk][r] = v[q].x; Bs[kk+1][r] = v[q].y; Bs[kk+2][r] = v[q].z; Bs[kk+3][r] = v[q].w;
        }
    };

    unsigned long long acc[4][8];
#pragma unroll
    for (int p = 0; p < 4; p++)
#pragma unroll
        for (int c = 0; c < 8; c++) acc[p][c] = 0ull;

    loadA(va, 0); loadB(vb, 0);
    storeA(va);   storeB(vb);
    __syncthreads();

    for (int t = 0; t < HH / 16; t++) {
        float4 na[2], nb[4];
        if (t < HH / 16 - 1) { loadA(na, (t + 1) * 16); loadB(nb, (t + 1) * 16); }
#pragma unroll 4
        for (int k = 0; k < 16; k++) {
            ulonglong2 a0 = *(const ulonglong2*)&As[k][mg * 8];
            ulonglong2 a1 = *(const ulonglong2*)&As[k][mg * 8 + 4];
            float4 w0 = *(const float4*)&Bs[k][ng * 8];
            float4 w1 = *(const float4*)&Bs[k][ng * 8 + 4];
            unsigned long long ap[4] = {a0.x, a0.y, a1.x, a1.y};
            unsigned long long bp[8] = {pack2(w0.x), pack2(w0.y), pack2(w0.z), pack2(w0.w),
                                        pack2(w1.x), pack2(w1.y), pack2(w1.z), pack2(w1.w)};
#pragma unroll
            for (int p = 0; p < 4; p++)
#pragma unroll
                for (int c = 0; c < 8; c++) ffma2(acc[p][c], ap[p], bp[c]);
        }
        __syncthreads();
        if (t < HH / 16 - 1) { storeA(na); storeB(nb); }
        __syncthreads();
    }

    // epilogue: add bias, write two rows per pair (vectorized float4)
    float4 bi0 = *(const float4*)(b_ih + n0 + ng * 8);
    float4 bi1 = *(const float4*)(b_ih + n0 + ng * 8 + 4);
    const int rowBase = by * BB;
#pragma unroll
    for (int p = 0; p < 4; p++) {
        float2 v[8];
#pragma unroll
        for (int c = 0; c < 8; c++) v[c] = unpk2(acc[p][c]);
        float* d0 = g_gi + (size_t)(rowBase + mg * 8 + 2 * p) * G3 + n0 + ng * 8;
        float* d1 = d0 + G3;
        *(float4*)(d0)     = make_float4(v[0].x + bi0.x, v[1].x + bi0.y, v[2].x + bi0.z, v[3].x + bi0.w);
        *(float4*)(d0 + 4) = make_float4(v[4].x + bi1.x, v[5].x + bi1.y, v[6].x + bi1.z, v[7].x + bi1.w);
        *(float4*)(d1)     = make_float4(v[0].y + bi0.x, v[1].y + bi0.y, v[2].y + bi0.z, v[3].y + bi0.w);
        *(float4*)(d1 + 4) = make_float4(v[4].y + bi1.x, v[5].y + bi1.y, v[6].y + bi1.z, v[7].y + bi1.w);
    }
}

// ---------------------------------------------------------------------------
// software grid barrier (monotonic, replay-safe)
__device__ __forceinline__ void gsync()
{
    __threadfence();
    __syncthreads();
    if (threadIdx.x == 0) {
        unsigned old = atomicAdd(&g_count, 1u) + 1u;
        if (old % RBLK == 0u) {
            atomicAdd(&g_gen, 1u);
        } else {
            unsigned target = (old + RBLK - 1u) / RBLK;
            volatile unsigned* vg = &g_gen;
            while (*vg < target) __nanosleep(20);
        }
    }
    __syncthreads();
}

// ---------------------------------------------------------------------------
// Persistent recurrence, SINGLE grid barrier per step.
// 96 blocks x 256 threads. Block owns hidden units u0..u0+7 -> 24 gh cols
// (col c = g*8+i <-> w_hh row g*768+u0+i). Gates computed block-locally from
// smem gh. h staged via double-buffered cp.async chunks of 256 k.
// Warp w = k-slice; lane: rg = lane&7 (rows rg*8..+7), cg = lane>>3 (cols cg*6..+5).
// dyn smem: ws 72KB + hs 2x64KB + ghs 6KB = 206KB.
__global__ void __launch_bounds__(RTPB, 1) k_rec(const float* __restrict__ w_hh,
                                                 const float* __restrict__ b_hh)
{
    extern __shared__ __align__(16) float sm[];
    float* ws  = sm;                       // [768][24]
    float* hs  = sm + HH * RC;             // 2 x [256][64]
    float* red = hs + CHK * BB;            // alias of hs buf1 (safe: see staging order)
    float* ghs = hs + 2 * CHK * BB;        // [64][24]

    const int tid  = threadIdx.x;
    const int u0   = blockIdx.x * UPB;
    const int w    = tid >> 5;             // 0..7
    const int lane = tid & 31;
    const int rg   = lane & 7;
    const int cg   = lane >> 3;            // 0..3

    // preload w slice: ws[k*24 + c], c = g*8+i  <->  w_hh[(g*768+u0+i)][k]
    for (int idx = tid; idx < HH * RC; idx += RTPB) {
        int k = idx / RC, c = idx - k * RC;
        int g = c >> 3, i = c & 7;
        ws[idx] = w_hh[(size_t)(g * HH + u0 + i) * HH + k];
    }
    // per-thread gate biases (2 gate slots: idx = tid, tid+256)
    float bh_r[2], bh_z[2], bh_n[2];
#pragma unroll
    for (int q = 0; q < 2; q++) {
        int idx = tid + q * RTPB;
        int i = idx & 7;
        bh_r[q] = b_hh[u0 + i];
        bh_z[q] = b_hh[HH + u0 + i];
        bh_n[q] = b_hh[2 * HH + u0 + i];
    }
    __syncthreads();

    const unsigned hsb = (unsigned)__cvta_generic_to_shared(hs);
    auto stage = [&](int ch) {
        const float4* src = (const float4*)(g_hT + (size_t)ch * CHK * BB) + tid;
        unsigned dst = hsb + (unsigned)((ch & 1) * (CHK * BB * 4)) + tid * 16;
#pragma unroll
        for (int j = 0; j < (CHK * BB / 4) / RTPB; j++)   // 16 iters
            cpa16(dst + j * RTPB * 16, src + j * RTPB);
        cpa_commit();
    };

    for (int l = 0; l < NSTEP; l++) {
        stage(0);
        stage(1);

        // prefetch gate operands into registers (resolve DRAM latency early)
        float pre_r[2], pre_z[2], pre_n[2], pre_h[2];
#pragma unroll
        for (int q = 0; q < 2; q++) {
            int idx = tid + q * RTPB;
            int b = idx >> 3, i = idx & 7;
            const float* gp = g_gi + ((size_t)l * BB + b) * G3 + u0 + i;
            pre_r[q] = __ldcg(gp);
            pre_z[q] = __ldcg(gp + HH);
            pre_n[q] = __ldcg(gp + 2 * HH);
            pre_h[q] = __ldcg(&g_hT[(u0 + i) * BB + b]);
        }

        unsigned long long acc[4][6];
#pragma unroll
        for (int p = 0; p < 4; p++)
#pragma unroll
            for (int c = 0; c < 6; c++) acc[p][c] = 0ull;

        for (int ch = 0; ch < HH / CHK; ch++) {
            if (ch < HH / CHK - 1) cpa_wait1(); else cpa_wait0();
            __syncthreads();
            const float* hb = hs + (ch & 1) * (CHK * BB);
            const int kb = w * (CHK / 8);
#pragma unroll 2
            for (int kk = 0; kk < CHK / 8; kk++) {
                const int kl = kb + kk;
                const int kg = ch * CHK + kl;
                ulonglong2 a0 = *(const ulonglong2*)&hb[kl * BB + rg * 8];
                ulonglong2 a1 = *(const ulonglong2*)&hb[kl * BB + rg * 8 + 4];
                const float* wp = &ws[kg * RC + cg * 6];
                float2 w01 = *(const float2*)(wp);
                float2 w23 = *(const float2*)(wp + 2);
                float2 w45 = *(const float2*)(wp + 4);
                unsigned long long ap[4] = {a0.x, a0.y, a1.x, a1.y};
                unsigned long long bp[6] = {pack2(w01.x), pack2(w01.y), pack2(w23.x),
                                            pack2(w23.y), pack2(w45.x), pack2(w45.y)};
#pragma unroll
                for (int p = 0; p < 4; p++)
#pragma unroll
                    for (int c = 0; c < 6; c++) ffma2(acc[p][c], ap[p], bp[c]);
            }
            __syncthreads();                 // release buffer (ch&1)
            if (ch == 0) stage(2);           // chunk2 -> buf0 (now free)
        }

        // ---- k-split reduction: warp partials -> red (buf1), then ghs ----
#pragma unroll
        for (int p = 0; p < 4; p++) {
            const int m0 = rg * 8 + 2 * p;
#pragma unroll
            for (int c = 0; c < 6; c++) {
                float2 v = unpk2(acc[p][c]);
                red[w * (BB * RC) + m0 * RC + cg * 6 + c]       = v.x;
                red[w * (BB * RC) + (m0 + 1) * RC + cg * 6 + c] = v.y;
            }
        }
        __syncthreads();
#pragma unroll
        for (int j = 0; j < (BB * RC) / RTPB; j++) {    // 6 outputs/thread
            const int o = tid + j * RTPB;
            float s = red[o];
#pragma unroll
            for (int ww = 1; ww < 8; ww++) s += red[ww * (BB * RC) + o];
            ghs[o] = s;
        }
        __syncthreads();

        // ---- gates (block-local) ----
#pragma unroll
        for (int q = 0; q < 2; q++) {
            const int idx = tid + q * RTPB;
            const int b = idx >> 3, i = idx & 7;
            float ghr = ghs[b * RC + i];
            float ghz = ghs[b * RC + 8 + i];
            float ghn = ghs[b * RC + 16 + i];
            float r = sigmoidf_(pre_r[q] + ghr + bh_r[q]);
            float z = sigmoidf_(pre_z[q] + ghz + bh_z[q]);
            float n = tanhf(pre_n[q] + r * (ghn + bh_n[q]));
            float h = (1.f - z) * n + z * pre_h[q];
            if (l < LL) h = fmaxf(h, 0.f);       // final step NOT relu'd
            __stcg(&g_hT[(u0 + i) * BB + b], h);
            if (l == LL) g_hbm[(size_t)b * HH + u0 + i] = h;
        }

        gsync();   // ONE barrier per step
    }
}

// ---------------------------------------------------------------------------
// Scorer: warp-per-neuron, weights in registers; device globals referenced
// directly in device code.
__global__ void __launch_bounds__(256) k_mlp0(const float* __restrict__ w,
                                              const float* __restrict__ bias)
{
    const int warp = threadIdx.x >> 5;
    const int lane = threadIdx.x & 31;
    const int n = blockIdx.x * 8 + warp;

    float4 wr[6];
    const float* wrow = w + (size_t)n * HH + lane * 24;
#pragma unroll
    for (int i = 0; i < 6; i++) wr[i] = *(const float4*)(wrow + i * 4);
    const float bn = bias[n];

    for (int b = 0; b < BB; b++) {
        const float* xr = g_hbm + (size_t)b * HH + lane * 24;
        float s = 0.f;
#pragma unroll
        for (int i = 0; i < 6; i++) {
            float4 xv = *(const float4*)(xr + i * 4);
            s += xv.x * wr[i].x + xv.y * wr[i].y + xv.z * wr[i].z + xv.w * wr[i].w;
        }
#pragma unroll
        for (int off = 16; off; off >>= 1) s += __shfl_xor_sync(0xffffffffu, s, off);
        if (lane == 0) g_s1[(size_t)b * HH + n] = fmaxf(s + bn, 0.f);
    }
}

__global__ void __launch_bounds__(256) k_mlp1(const float* __restrict__ w,
                                              const float* __restrict__ bias)
{
    const int warp = threadIdx.x >> 5;
    const int lane = threadIdx.x & 31;
    const int n = blockIdx.x * 8 + warp;

    float4 wr[6];
    const float* wrow = w + (size_t)n * HH + lane * 24;
#pragma unroll
    for (int i = 0; i < 6; i++) wr[i] = *(const float4*)(wrow + i * 4);
    const float bn = bias[n];

    for (int b = 0; b < BB; b++) {
        const float* xr = g_s1 + (size_t)b * HH + lane * 24;
        float s = 0.f;
#pragma unroll
        for (int i = 0; i < 6; i++) {
            float4 xv = *(const float4*)(xr + i * 4);
            s += xv.x * wr[i].x + xv.y * wr[i].y + xv.z * wr[i].z + xv.w * wr[i].w;
        }
#pragma unroll
        for (int off = 16; off; off >>= 1) s += __shfl_xor_sync(0xffffffffu, s, off);
        if (lane == 0) g_s2[(size_t)b * HH + n] = fmaxf(s + bn, 0.f);
    }
}

__global__ void __launch_bounds__(256) k_final(const float* __restrict__ swo,
                                               const float* __restrict__ sbo,
                                               float* __restrict__ out)
{
    const int warp = threadIdx.x >> 5;
    const int lane = threadIdx.x & 31;
    const int b = blockIdx.x * 8 + warp;
    const float* xr = g_s2 + (size_t)b * HH + lane * 24;
    const float* wr = swo + lane * 24;
    float s = 0.f;
#pragma unroll
    for (int i = 0; i < 6; i++) {
        float4 xv = *(const float4*)(xr + i * 4);
        float4 wv = *(const float4*)(wr + i * 4);
        s += xv.x * wv.x + xv.y * wv.y + xv.z * wv.z + xv.w * wv.w;
    }
#pragma unroll
    for (int off = 16; off; off >>= 1) s += __shfl_xor_sync(0xffffffffu, s, off);
    if (lane == 0) out[b] = s + sbo[0];
}

// ---------------------------------------------------------------------------
extern "C" void kernel_launch(void* const* d_in, const int* in_sizes, int n_in,
                              void* d_out, int out_size)
{
    const int*   goal = (const int*)  d_in[0];
    const float* emb  = (const float*)d_in[1];
    const float* w_ih = (const float*)d_in[2];
    const float* w_hh = (const float*)d_in[3];
    const float* b_ih = (const float*)d_in[4];
    const float* b_hh = (const float*)d_in[5];
    const float* sw0  = (const float*)d_in[6];
    const float* sb0  = (const float*)d_in[7];
    const float* sw1  = (const float*)d_in[8];
    const float* sb1  = (const float*)d_in[9];
    const float* swo  = (const float*)d_in[10];
    const float* sbo  = (const float*)d_in[11];
    float* out = (float*)d_out;

    const int smem_rec = (HH * RC + 2 * CHK * BB + BB * RC) * (int)sizeof(float); // 206KB
    cudaFuncSetAttribute(k_rec, cudaFuncAttributeMaxDynamicSharedMemorySize, smem_rec);

    k_init<<<(BB * HH + 255) / 256, 256>>>();
    k_gi<<<dim3(G3 / 128, NSTEP), 128>>>(goal, emb, w_ih, b_ih);
    k_rec<<<RBLK, RTPB, smem_rec>>>(w_hh, b_hh);
    k_mlp0<<<HH / 8, 256>>>(sw0, sb0);
    k_mlp1<<<HH / 8, 256>>>(sw1, sb1);
    k_final<<<BB / 8, 256>>>(swo, sbo, out);
}

// round 7
// speedup vs baseline: 1.9344x; 1.2614x over previous
#include <cuda_runtime.h>
#include <cuda_bf16.h>
#include <math.h>

// Problem dims (fixed)
#define HH 768
#define G3 2304          // 3*H
#define BB 64            // batch
#define LL 512           // seq len
#define NSTEP 513        // 512 steps + final end-token step
#define NROWS (NSTEP*BB)

// recurrence kernel config
#define RBLK 128         // persistent blocks (16 leaves x 8)
#define RTPB 256
#define UPB  6           // hidden units per block (128*6=768)
#define RC   18          // gh cols per block = 3*UPB
#define RCP  24          // padded ws row: 2 groups x 12 (9 used)
#define CHK  256         // staged k rows per buffer (768 = 3*256)

// Scratch (device globals — allocation-free rule)
static __device__ __align__(256) float g_giT[(size_t)NROWS * G3];  // gi transposed: [l][G3 unit][64 b]
static __device__ __align__(256) float g_hT[HH * BB];              // h transposed [k][b]
static __device__ __align__(256) float g_hbm[BB * HH];             // final h [b][k] for scorer
static __device__ __align__(256) float g_s1[BB * HH];
static __device__ __align__(256) float g_s2[BB * HH];
static __device__ unsigned g_leaf[16];                             // monotonic leaf counters
static __device__ unsigned g_master = 0;                           // monotonic master counter
static __device__ unsigned g_gen    = 0;                           // monotonic generation

// ---------------------------------------------------------------------------
// packed fp32 helpers (sm_103a f32x2)
__device__ __forceinline__ void ffma2(unsigned long long& d,
                                      unsigned long long a, unsigned long long b)
{
    asm("fma.rn.f32x2 %0, %1, %2, %0;" : "+l"(d) : "l"(a), "l"(b));
}
__device__ __forceinline__ unsigned long long pack2(float x)
{
    unsigned long long r;
    asm("mov.b64 %0, {%1, %1};" : "=l"(r) : "f"(x));
    return r;
}
__device__ __forceinline__ float2 unpk2(unsigned long long v)
{
    float2 f;
    asm("mov.b64 {%0, %1}, %2;" : "=f"(f.x), "=f"(f.y) : "l"(v));
    return f;
}
__device__ __forceinline__ void cpa16(unsigned dst, const void* src)
{
    asm volatile("cp.async.cg.shared.global [%0], [%1], 16;" :: "r"(dst), "l"(src));
}
__device__ __forceinline__ void cpa_commit() { asm volatile("cp.async.commit_group;" ::: "memory"); }
__device__ __forceinline__ void cpa_wait0()  { asm volatile("cp.async.wait_group 0;" ::: "memory"); }
__device__ __forceinline__ void cpa_wait1()  { asm volatile("cp.async.wait_group 1;" ::: "memory"); }

__device__ __forceinline__ float sigmoidf_(float x)
{
    return 1.f / (1.f + __expf(-x));
}

// ---------------------------------------------------------------------------
__global__ void k_init()
{
    int t = blockIdx.x * blockDim.x + threadIdx.x;
    if (t < BB * HH) g_hT[t] = 0.f;
}

// ---------------------------------------------------------------------------
// giT[l][unit][b] = relu_if_seq(emb[token(b,l)]) . w_ih[unit,:] + b_ih[unit]
// Output-transposed gemm: M=units (128/block, f32x2 pairs), N=batch (64).
// 128 threads, thread tile 8u x 8b, register double-buffered loads.
__global__ void __launch_bounds__(128) k_gi(const int* __restrict__ goal,
                                            const float* __restrict__ emb,
                                            const float* __restrict__ w_ih,
                                            const float* __restrict__ b_ih)
{
    __shared__ __align__(16) float As[16][128];   // units x k
    __shared__ __align__(16) float Bs[16][64];    // batch x k
    __shared__ int tok[64];

    const int by  = blockIdx.y;        // step index
    const int n0  = blockIdx.x * 128;  // unit base
    const int tid = threadIdx.x;
    const bool seq = (by < LL);

    if (tid < 64) tok[tid] = seq ? goal[tid * LL + by] : 1;
    __syncthreads();

    const int ug = tid & 15;           // unit group -> units ug*8..+7
    const int bg = tid >> 4;           // batch group -> batch bg*8..+7

    float4 vw[4], ve[2];
    auto loadW = [&](float4 v[4], int k0) {
#pragma unroll
        for (int q = 0; q < 4; q++) {
            int f = tid + 128 * q;
            int r = f >> 2, kk = (f & 3) * 4;
            v[q] = *(const float4*)(w_ih + (size_t)(n0 + r) * HH + k0 + kk);
        }
    };
    auto loadE = [&](float4 v[2], int k0) {
#pragma unroll
        for (int q = 0; q < 2; q++) {
            int f = tid + 128 * q;
            int r = f >> 2, kk = (f & 3) * 4;
            v[q] = *(const float4*)(emb + (size_t)tok[r] * HH + k0 + kk);
            if (seq) {
                v[q].x = fmaxf(v[q].x, 0.f); v[q].y = fmaxf(v[q].y, 0.f);
                v[q].z = fmaxf(v[q].z, 0.f); v[q].w = fmaxf(v[q].w, 0.f);
            }
        }
    };
    auto storeW = [&](const float4 v[4]) {
#pragma unroll
        for (int q = 0; q < 4; q++) {
            int f = tid + 128 * q;
            int r = f >> 2, kk = (f & 3) * 4;
            As[kk][r] = v[q].x; As[kk+1][r] = v[q].y; As[kk+2][r] = v[q].z; As[kk+3][r] = v[q].w;
        }
    };
    auto storeE = [&](const float4 v[2]) {
#pragma unroll
        for (int q = 0; q < 2; q++) {
            int f = tid + 128 * q;
            int r = f >> 2, kk = (f & 3) * 4;
            Bs[kk][r] = v[q].x; Bs[kk+1][r] = v[q].y; Bs[kk+2][r] = v[q].z; Bs[kk+3][r] = v[q].w;
        }
    };

    unsigned long long acc[4][8];
#pragma unroll
    for (int p = 0; p < 4; p++)
#pragma unroll
        for (int c = 0; c < 8; c++) acc[p][c] = 0ull;

    loadW(vw, 0); loadE(ve, 0);
    storeW(vw);   storeE(ve);
    __syncthreads();

    for (int t = 0; t < HH / 16; t++) {
        float4 nw[4], ne[2];
        if (t < HH / 16 - 1) { loadW(nw, (t + 1) * 16); loadE(ne, (t + 1) * 16); }
#pragma unroll 4
        for (int k = 0; k < 16; k++) {
            ulonglong2 a0 = *(const ulonglong2*)&As[k][ug * 8];
            ulonglong2 a1 = *(const ulonglong2*)&As[k][ug * 8 + 4];
            float4 e0 = *(const float4*)&Bs[k][bg * 8];
            float4 e1 = *(const float4*)&Bs[k][bg * 8 + 4];
            unsigned long long ap[4] = {a0.x, a0.y, a1.x, a1.y};
            unsigned long long bp[8] = {pack2(e0.x), pack2(e0.y), pack2(e0.z), pack2(e0.w),
                                        pack2(e1.x), pack2(e1.y), pack2(e1.z), pack2(e1.w)};
#pragma unroll
            for (int p = 0; p < 4; p++)
#pragma unroll
                for (int c = 0; c < 8; c++) ffma2(acc[p][c], ap[p], bp[c]);
        }
        __syncthreads();
        if (t < HH / 16 - 1) { storeW(nw); storeE(ne); }
        __syncthreads();
    }

    // epilogue: giT[(by*G3 + unit)*64 + batch] (+ per-unit bias)
#pragma unroll
    for (int p = 0; p < 4; p++) {
        const int u0 = n0 + ug * 8 + 2 * p;
        float bia0 = b_ih[u0], bia1 = b_ih[u0 + 1];
        float2 v[8];
#pragma unroll
        for (int c = 0; c < 8; c++) v[c] = unpk2(acc[p][c]);
        float* d0 = g_giT + ((size_t)by * G3 + u0) * BB + bg * 8;
        float* d1 = d0 + BB;
        *(float4*)(d0)     = make_float4(v[0].x + bia0, v[1].x + bia0, v[2].x + bia0, v[3].x + bia0);
        *(float4*)(d0 + 4) = make_float4(v[4].x + bia0, v[5].x + bia0, v[6].x + bia0, v[7].x + bia0);
        *(float4*)(d1)     = make_float4(v[0].y + bia1, v[1].y + bia1, v[2].y + bia1, v[3].y + bia1);
        *(float4*)(d1 + 4) = make_float4(v[4].y + bia1, v[5].y + bia1, v[6].y + bia1, v[7].y + bia1);
    }
}

// ---------------------------------------------------------------------------
// Two-level grid barrier: 16 leaf counters (8 blocks each) -> master -> gen.
// Release/acquire chain; monotonic counters + base read at launch (replay-safe).
__device__ __forceinline__ void gsync(unsigned target)
{
    __syncthreads();
    if (threadIdx.x == 0) {
        unsigned old;
        asm volatile("atom.acq_rel.gpu.global.add.u32 %0, [%1], %2;"
                     : "=r"(old) : "l"(g_leaf + (blockIdx.x & 15u)), "r"(1u) : "memory");
        if ((old & 7u) == 7u) {
            unsigned o2;
            asm volatile("atom.acq_rel.gpu.global.add.u32 %0, [%1], %2;"
                         : "=r"(o2) : "l"(&g_master), "r"(1u) : "memory");
            if ((o2 & 15u) == 15u)
                asm volatile("st.release.gpu.global.u32 [%0], %1;"
                             :: "l"(&g_gen), "r"(target) : "memory");
        }
        unsigned g;
        do {
            asm volatile("ld.acquire.gpu.global.u32 %0, [%1];"
                         : "=r"(g) : "l"(&g_gen) : "memory");
        } while ((int)(g - target) < 0);
    }
    __syncthreads();
}

// ---------------------------------------------------------------------------
// Persistent recurrence, 128 blocks x 256 threads, ONE barrier per step.
// Block owns 6 hidden units -> 18 gh cols (col = gate*6 + unit).
// 8 warps k-split (96 k each); lane: rg=lane&15 (4 rows), cg=lane>>4 (9 cols).
// smem: ws[768][24] 72KB + hs 2x64KB + ghs 4.5KB = 204.5KB.
__global__ void __launch_bounds__(RTPB, 1) k_rec(const float* __restrict__ w_hh,
                                                 const float* __restrict__ b_hh)
{
    extern __shared__ __align__(16) float sm[];
    float* ws  = sm;                       // [768][24] padded
    float* hs  = sm + HH * RCP;            // 2 x [256][64]
    float* red = hs + CHK * BB;            // alias buf1 (free when reduction runs)
    float* ghs = hs + 2 * CHK * BB;        // [64][18]

    const int tid  = threadIdx.x;
    const int u0   = blockIdx.x * UPB;
    const int w    = tid >> 5;             // warp = k-slice 0..7
    const int lane = tid & 31;
    const int rg   = lane & 15;            // rows rg*4..+3 (2 f32x2 pairs)
    const int cg   = lane >> 4;            // cols cg*9..+8

    // preload w slice: ws[k*24 + cg*12 + c] = w_hh[(gate*768 + u0+unit)][k], col=cg*9+c
    for (int idx = tid; idx < HH * RCP; idx += RTPB) {
        int k = idx / RCP, cc = idx - k * RCP;
        int g2 = cc / 12, c = cc - g2 * 12;
        float v = 0.f;
        if (c < 9) {
            int col = g2 * 9 + c;
            int gate = col / UPB, unit = col - gate * UPB;
            v = w_hh[(size_t)(gate * HH + u0 + unit) * HH + k];
        }
        ws[idx] = v;
    }
    // gate biases: mapping t = tid + q*256 -> b = t&63, iu = t>>6 (<6)
    float bh_r[2], bh_z[2], bh_n[2];
#pragma unroll
    for (int q = 0; q < 2; q++) {
        int t = tid + q * RTPB;
        if (t < BB * UPB) {
            int iu = t >> 6;
            bh_r[q] = b_hh[u0 + iu];
            bh_z[q] = b_hh[HH + u0 + iu];
            bh_n[q] = b_hh[2 * HH + u0 + iu];
        }
    }
    __syncthreads();

    const unsigned hsb = (unsigned)__cvta_generic_to_shared(hs);
    auto stage = [&](int ch) {
        const float4* src = (const float4*)(g_hT + (size_t)ch * CHK * BB) + tid;
        unsigned dst = hsb + (unsigned)((ch & 1) * (CHK * BB * 4)) + tid * 16;
#pragma unroll
        for (int j = 0; j < (CHK * BB / 4) / RTPB; j++)   // 16
            cpa16(dst + j * RTPB * 16, src + j * RTPB);
        cpa_commit();
    };

    const unsigned base = *(volatile unsigned*)&g_gen;    // replay-safe offset
    unsigned ngen = 0;

    for (int l = 0; l < NSTEP; l++) {
        stage(0);
        stage(1);

        // prefetch gate operands (coalesced: batch-contiguous)
        float pre_r[2], pre_z[2], pre_n[2], pre_h[2];
#pragma unroll
        for (int q = 0; q < 2; q++) {
            int t = tid + q * RTPB;
            if (t < BB * UPB) {
                int b = t & 63, iu = t >> 6;
                const float* gp = g_giT + ((size_t)l * G3 + u0 + iu) * BB + b;
                pre_r[q] = __ldcg(gp);
                pre_z[q] = __ldcg(gp + (size_t)HH * BB);
                pre_n[q] = __ldcg(gp + (size_t)2 * HH * BB);
                pre_h[q] = __ldcg(&g_hT[(u0 + iu) * BB + b]);
            }
        }

        unsigned long long acc[2][9];
#pragma unroll
        for (int p = 0; p < 2; p++)
#pragma unroll
            for (int c = 0; c < 9; c++) acc[p][c] = 0ull;

        for (int ch = 0; ch < HH / CHK; ch++) {
            if (ch < HH / CHK - 1) cpa_wait1(); else cpa_wait0();
            __syncthreads();
            const float* hb = hs + (ch & 1) * (CHK * BB);
            const int kb = w * (CHK / 8);
#pragma unroll 4
            for (int kk = 0; kk < CHK / 8; kk++) {
                const int kl = kb + kk;
                const int kg = ch * CHK + kl;
                ulonglong2 a = *(const ulonglong2*)&hb[kl * BB + rg * 4];
                const float* wp = &ws[kg * RCP + cg * 12];
                float4 w0 = *(const float4*)(wp);
                float4 w1 = *(const float4*)(wp + 4);
                float  w8 = wp[8];
                unsigned long long bp[9] = {pack2(w0.x), pack2(w0.y), pack2(w0.z), pack2(w0.w),
                                            pack2(w1.x), pack2(w1.y), pack2(w1.z), pack2(w1.w),
                                            pack2(w8)};
#pragma unroll
                for (int c = 0; c < 9; c++) {
                    ffma2(acc[0][c], a.x, bp[c]);
                    ffma2(acc[1][c], a.y, bp[c]);
                }
            }
            __syncthreads();                 // buffer (ch&1) free
            if (ch == 0) stage(2);           // chunk2 -> buf0
        }

        // ---- k-split reduction: red[w][64][18] (buf1), then ghs[64][18] ----
#pragma unroll
        for (int p = 0; p < 2; p++) {
            const int r0 = rg * 4 + 2 * p;
#pragma unroll
            for (int c = 0; c < 9; c++) {
                float2 v = unpk2(acc[p][c]);
                red[w * (BB * RC) + r0 * RC + cg * 9 + c]       = v.x;
                red[w * (BB * RC) + (r0 + 1) * RC + cg * 9 + c] = v.y;
            }
        }
        __syncthreads();
#pragma unroll
        for (int j = 0; j < 5; j++) {
            const int o = tid + j * RTPB;
            if (o < BB * RC) {
                float s = red[o];
#pragma unroll
                for (int ww = 1; ww < 8; ww++) s += red[ww * (BB * RC) + o];
                ghs[o] = s;
            }
        }
        __syncthreads();

        // ---- gates (block-local, coalesced h stores) ----
#pragma unroll
        for (int q = 0; q < 2; q++) {
            const int t = tid + q * RTPB;
            if (t < BB * UPB) {
                const int b = t & 63, iu = t >> 6;
                float ghr = ghs[b * RC + iu];
                float ghz = ghs[b * RC + UPB + iu];
                float ghn = ghs[b * RC + 2 * UPB + iu];
                float r = sigmoidf_(pre_r[q] + ghr + bh_r[q]);
                float z = sigmoidf_(pre_z[q] + ghz + bh_z[q]);
                float n = tanhf(pre_n[q] + r * (ghn + bh_n[q]));
                float h = (1.f - z) * n + z * pre_h[q];
                if (l < LL) h = fmaxf(h, 0.f);     // final step NOT relu'd
                __stcg(&g_hT[(u0 + iu) * BB + b], h);
                if (l == LL) g_hbm[(size_t)b * HH + u0 + iu] = h;
            }
        }

        ++ngen;
        gsync(base + ngen);   // ONE barrier per step
    }
}

// ---------------------------------------------------------------------------
// Scorer: warp-per-neuron, weights in registers; device globals referenced
// directly in device code (host may not pass __device__ symbols).
__global__ void __launch_bounds__(256) k_mlp0(const float* __restrict__ w,
                                              const float* __restrict__ bias)
{
    const int warp = threadIdx.x >> 5;
    const int lane = threadIdx.x & 31;
    const int n = blockIdx.x * 8 + warp;

    float4 wr[6];
    const float* wrow = w + (size_t)n * HH + lane * 24;
#pragma unroll
    for (int i = 0; i < 6; i++) wr[i] = *(const float4*)(wrow + i * 4);
    const float bn = bias[n];

    for (int b = 0; b < BB; b++) {
        const float* xr = g_hbm + (size_t)b * HH + lane * 24;
        float s = 0.f;
#pragma unroll
        for (int i = 0; i < 6; i++) {
            float4 xv = *(const float4*)(xr + i * 4);
            s += xv.x * wr[i].x + xv.y * wr[i].y + xv.z * wr[i].z + xv.w * wr[i].w;
        }
#pragma unroll
        for (int off = 16; off; off >>= 1) s += __shfl_xor_sync(0xffffffffu, s, off);
        if (lane == 0) g_s1[(size_t)b * HH + n] = fmaxf(s + bn, 0.f);
    }
}

__global__ void __launch_bounds__(256) k_mlp1(const float* __restrict__ w,
                                              const float* __restrict__ bias)
{
    const int warp = threadIdx.x >> 5;
    const int lane = threadIdx.x & 31;
    const int n = blockIdx.x * 8 + warp;

    float4 wr[6];
    const float* wrow = w + (size_t)n * HH + lane * 24;
#pragma unroll
    for (int i = 0; i < 6; i++) wr[i] = *(const float4*)(wrow + i * 4);
    const float bn = bias[n];

    for (int b = 0; b < BB; b++) {
        const float* xr = g_s1 + (size_t)b * HH + lane * 24;
        float s = 0.f;
#pragma unroll
        for (int i = 0; i < 6; i++) {
            float4 xv = *(const float4*)(xr + i * 4);
            s += xv.x * wr[i].x + xv.y * wr[i].y + xv.z * wr[i].z + xv.w * wr[i].w;
        }
#pragma unroll
        for (int off = 16; off; off >>= 1) s += __shfl_xor_sync(0xffffffffu, s, off);
        if (lane == 0) g_s2[(size_t)b * HH + n] = fmaxf(s + bn, 0.f);
    }
}

__global__ void __launch_bounds__(256) k_final(const float* __restrict__ swo,
                                               const float* __restrict__ sbo,
                                               float* __restrict__ out)
{
    const int warp = threadIdx.x >> 5;
    const int lane = threadIdx.x & 31;
    const int b = blockIdx.x * 8 + warp;
    const float* xr = g_s2 + (size_t)b * HH + lane * 24;
    const float* wr = swo + lane * 24;
    float s = 0.f;
#pragma unroll
    for (int i = 0; i < 6; i++) {
        float4 xv = *(const float4*)(xr + i * 4);
        float4 wv = *(const float4*)(wr + i * 4);
        s += xv.x * wv.x + xv.y * wv.y + xv.z * wv.z + xv.w * wv.w;
    }
#pragma unroll
    for (int off = 16; off; off >>= 1) s += __shfl_xor_sync(0xffffffffu, s, off);
    if (lane == 0) out[b] = s + sbo[0];
}

// ---------------------------------------------------------------------------
extern "C" void kernel_launch(void* const* d_in, const int* in_sizes, int n_in,
                              void* d_out, int out_size)
{
    const int*   goal = (const int*)  d_in[0];
    const float* emb  = (const float*)d_in[1];
    const float* w_ih = (const float*)d_in[2];
    const float* w_hh = (const float*)d_in[3];
    const float* b_ih = (const float*)d_in[4];
    const float* b_hh = (const float*)d_in[5];
    const float* sw0  = (const float*)d_in[6];
    const float* sb0  = (const float*)d_in[7];
    const float* sw1  = (const float*)d_in[8];
    const float* sb1  = (const float*)d_in[9];
    const float* swo  = (const float*)d_in[10];
    const float* sbo  = (const float*)d_in[11];
    float* out = (float*)d_out;

    const int smem_rec = (HH * RCP + 2 * CHK * BB + BB * RC) * (int)sizeof(float); // 204.5KB
    cudaFuncSetAttribute(k_rec, cudaFuncAttributeMaxDynamicSharedMemorySize, smem_rec);

    k_init<<<(BB * HH + 255) / 256, 256>>>();
    k_gi<<<dim3(G3 / 128, NSTEP), 128>>>(goal, emb, w_ih, b_ih);
    k_rec<<<RBLK, RTPB, smem_rec>>>(w_hh, b_hh);
    k_mlp0<<<HH / 8, 256>>>(sw0, sb0);
    k_mlp1<<<HH / 8, 256>>>(sw1, sb1);
    k_final<<<BB / 8, 256>>>(swo, sbo, out);
}